// round 13
// baseline (speedup 1.0000x reference)
#include <cuda_runtime.h>
#include <cuda_bf16.h>
#include <cstdint>
#include <math.h>

#define S_LEN 4096
#define DM    1024
#define NH    16
#define HD    64
#define WIN   64

// ---------------- device scratch (no allocations allowed) ----------------
__device__ float g_q  [S_LEN * DM];
__device__ float g_k  [S_LEN * DM];
__device__ float g_v  [S_LEN * DM];
__device__ float g_xr [S_LEN * DM];
__device__ float g_wr [4 * DM * DM];
__device__ float g_aor[S_LEN * DM];

// ---------------- PTX helpers ----------------
__device__ __forceinline__ uint32_t smem_u32(const void* p) {
    uint32_t a;
    asm("{ .reg .u64 t; cvta.to.shared.u64 t, %1; cvt.u32.u64 %0, t; }" : "=r"(a) : "l"(p));
    return a;
}
#define CP16(dst, src) \
    asm volatile("cp.async.cg.shared.global [%0], [%1], 16;" :: "r"((uint32_t)(dst)), "l"(src) : "memory")
#define CP_COMMIT() asm volatile("cp.async.commit_group;" ::: "memory")
#define CP_WAIT1()  asm volatile("cp.async.wait_group 1;" ::: "memory")

#define LDSM4(r, addr) \
    asm volatile("ldmatrix.sync.aligned.m8n8.x4.shared.b16 {%0,%1,%2,%3}, [%4];" \
        : "=r"((r)[0]), "=r"((r)[1]), "=r"((r)[2]), "=r"((r)[3]) : "r"(addr))

#define MMA_TF32(d, a, b0v, b1v) \
    asm volatile("mma.sync.aligned.m16n8k8.row.col.f32.tf32.tf32.f32 " \
        "{%0,%1,%2,%3}, {%4,%5,%6,%7}, {%8,%9}, {%0,%1,%2,%3};" \
        : "+f"((d)[0]), "+f"((d)[1]), "+f"((d)[2]), "+f"((d)[3]) \
        : "r"((a)[0]), "r"((a)[1]), "r"((a)[2]), "r"((a)[3]), "r"(b0v), "r"(b1v))

__device__ __forceinline__ float tf32_rna(float x) {
    uint32_t t;
    asm("cvt.rna.tf32.f32 %0, %1;" : "=r"(t) : "f"(x));
    return __uint_as_float(t);
}

// ---------------- merged tf32 pre-round kernel ----------------
__global__ void round_all(const float* __restrict__ x,
                          const float* __restrict__ Wq, const float* __restrict__ Wk,
                          const float* __restrict__ Wv, const float* __restrict__ Wo,
                          float* __restrict__ xr, float* __restrict__ wr) {
    const int y = blockIdx.y;
    const float* src;
    float* dst;
    if (y < 4) {
        src = x  + (size_t)y * (S_LEN * DM / 4);
        dst = xr + (size_t)y * (S_LEN * DM / 4);
    } else {
        const float* W = y == 4 ? Wq : (y == 5 ? Wk : (y == 6 ? Wv : Wo));
        src = W;
        dst = wr + (size_t)(y - 4) * DM * DM;
    }
    int i = blockIdx.x * blockDim.x + threadIdx.x;
    float4 f = ((const float4*)src)[i];
    ((float4*)dst)[i] = make_float4(tf32_rna(f.x), tf32_rna(f.y), tf32_rna(f.z), tf32_rna(f.w));
}

// ---------------------------------------------------------------------------
// tf32 GEMM v7 (FROZEN from R11).
// ---------------------------------------------------------------------------
#define TILE_B  16384
#define STAGE_B (2 * TILE_B)
#define NSTAGE  3
#define GEMM_SMEM (NSTAGE * STAGE_B)

__global__ __launch_bounds__(128, 2) void gemm_tf32(
    const float* __restrict__ A, const float* __restrict__ Wr,
    int w_off, int nz,
    float* __restrict__ C0, float* __restrict__ C1, float* __restrict__ C2)
{
    extern __shared__ char sm[];
    const uint32_t smem_base = smem_u32(sm);
    const int tid  = threadIdx.x;
    const int lane = tid & 31;
    const int wid  = tid >> 5;
    const int wm   = wid & 1;
    const int wn   = wid >> 1;
    const int m0 = blockIdx.y * 128;
    const int n0 = blockIdx.x * 128;

    uint32_t swo[8], gA[8], gB[8];
#pragma unroll
    for (int jj = 0; jj < 8; jj++) {
        int qq = tid + 128 * jj;
        int r = qq >> 3, c = qq & 7;
        swo[jj] = (uint32_t)(r * 128 + ((c ^ (r & 7)) << 4));
        gA[jj] = (uint32_t)((m0 + r) * DM + c * 4);
        gB[jj] = (uint32_t)((n0 + r) * DM + c * 4);
    }

    const int lm   = lane >> 3;
    const int lrow = lane & 7;
    const int cSel = lm >> 1;
    uint32_t aOff[4]; int aXor[4];
#pragma unroll
    for (int mi = 0; mi < 4; mi++) {
        int ar = wm * 64 + mi * 16 + (lm & 1) * 8 + lrow;
        aOff[mi] = (uint32_t)(ar * 128); aXor[mi] = ar & 7;
    }
    uint32_t bOff[4]; int bXor[4];
#pragma unroll
    for (int pb = 0; pb < 4; pb++) {
        int br = wn * 64 + pb * 16 + (lm & 1) * 8 + lrow;
        bOff[pb] = (uint32_t)(br * 128); bXor[pb] = br & 7;
    }

    const int ITERS = DM / 32;

    for (int zi = 0; zi < nz; zi++) {
        const float* B = Wr + (size_t)(w_off + zi) * DM * DM;
        float* C = zi == 0 ? C0 : (zi == 1 ? C1 : C2);

        float acc[4][8][4];
#pragma unroll
        for (int mi = 0; mi < 4; mi++)
#pragma unroll
            for (int nb = 0; nb < 8; nb++)
#pragma unroll
                for (int e2 = 0; e2 < 4; e2++) acc[mi][nb][e2] = 0.0f;

        auto issue = [&](int t) {
            const uint32_t sb = smem_base + (uint32_t)(t % NSTAGE) * STAGE_B;
            const uint32_t kt = (uint32_t)(t * 32);
#pragma unroll
            for (int jj = 0; jj < 8; jj++) {
                CP16(sb + swo[jj],          (const char*)A + (size_t)(gA[jj] + kt) * 4);
                CP16(sb + TILE_B + swo[jj], (const char*)B + (size_t)(gB[jj] + kt) * 4);
            }
            CP_COMMIT();
        };

        __syncthreads();
        issue(0); issue(1);

        for (int t = 0; t < ITERS; t++) {
            CP_WAIT1();
            __syncthreads();
            if (t + 2 < ITERS) issue(t + 2);

            const uint32_t sb = smem_base + (uint32_t)(t % NSTAGE) * STAGE_B;
            const uint32_t aBase = sb, bBase = sb + TILE_B;

#pragma unroll
            for (int s = 0; s < 4; s++) {
                uint32_t fA[4][4];
#pragma unroll
                for (int mi = 0; mi < 4; mi++)
                    LDSM4(fA[mi], aBase + aOff[mi] + (uint32_t)((((2 * s) + cSel) ^ aXor[mi]) << 4));
                uint32_t fB[8][2];
#pragma unroll
                for (int pb = 0; pb < 4; pb++) {
                    uint32_t bt[4];
                    LDSM4(bt, bBase + bOff[pb] + (uint32_t)((((2 * s) + cSel) ^ bXor[pb]) << 4));
                    fB[2 * pb][0] = bt[0]; fB[2 * pb][1] = bt[2];
                    fB[2 * pb + 1][0] = bt[1]; fB[2 * pb + 1][1] = bt[3];
                }
#pragma unroll
                for (int mi = 0; mi < 4; mi++)
#pragma unroll
                    for (int nb = 0; nb < 8; nb++)
                        MMA_TF32(acc[mi][nb], fA[mi], fB[nb][0], fB[nb][1]);
            }
        }

        const int crow0 = m0 + wm * 64 + (lane >> 2);
        const int ccol0 = n0 + wn * 64 + (lane & 3) * 2;
#pragma unroll
        for (int mi = 0; mi < 4; mi++) {
#pragma unroll
            for (int nb = 0; nb < 8; nb++) {
                const int row = crow0 + mi * 16;
                const int col = ccol0 + nb * 8;
                *(float2*)&C[(size_t)row * DM + col]       = make_float2(acc[mi][nb][0], acc[mi][nb][1]);
                *(float2*)&C[(size_t)(row + 8) * DM + col] = make_float2(acc[mi][nb][2], acc[mi][nb][3]);
            }
        }
    }
}

// ---------------------------------------------------------------------------
// Sliding-window attention v6: tensor-core QK + scalar AV.
// Block = 64 queries x 1 head, 128 threads (4 warps).
// GEMM1: S[64x128] = Q(A-tiles, pre-scaled 1/8) x K(B-tiles) via mma.tf32;
// warp wid owns score cols [32*wid, 32*wid+32).  Band mask in C-frags,
// softmax via frag reduce + shfl(1,2) + cross-warp smem reduce, P scattered
// to Ps[q][w=col-row] (stride 67) — consumed by the R7-proven scalar AV.
// smem: Q-tiles 16KB | K-tiles 32KB | Vs 34.5KB | red 2KB; Ps overlays Q/K.
// ---------------------------------------------------------------------------
#define ATT_PAD 68
#define PS_STR 67
#define V_OFF_F 12288                      // float index of Vs (byte 49152)
#define RED1_B  83696
#define RED2_B  84720
#define ATT_SMEM_BYTES 85744

__global__ __launch_bounds__(128, 2) void swattn(
    const float* __restrict__ q, const float* __restrict__ k,
    const float* __restrict__ v, float* __restrict__ o)
{
    extern __shared__ float smf[];
    char* smc = (char*)smf;
    const uint32_t smem_base = smem_u32(smf);
    float* Vs   = smf + V_OFF_F;           // [127][68]
    float* Ps   = smf;                     // overlays Q/K tiles after GEMM1
    float* red1 = (float*)(smc + RED1_B);  // [4][64]
    float* red2 = (float*)(smc + RED2_B);  // [4][64]

    const int qstart  = blockIdx.x * 64;
    const int h       = blockIdx.y;
    const int korigin = qstart - (WIN - 1);
    const int hcol    = h * HD;

    const int tid  = threadIdx.x;
    const int lane = tid & 31;
    const int wid  = tid >> 5;

    // ---- fill Q A-tiles: 2 x [64 rows x 32 floats], pre-scaled 1/8 ----
    for (int idx = tid; idx < 64 * 16; idx += 128) {
        int row = idx >> 4, c = idx & 15;
        int kc = c >> 3, cc = c & 7;
        float4 t = *(const float4*)&q[(size_t)(qstart + row) * DM + hcol + kc * 32 + cc * 4];
        t.x *= 0.125f; t.y *= 0.125f; t.z *= 0.125f; t.w *= 0.125f;
        *(float4*)(smc + kc * 8192 + row * 128 + ((cc ^ (row & 7)) << 4)) = t;
    }
    // ---- fill K B-tiles: 2 x [128 rows x 32 floats], zero OOR ----
    for (int idx = tid; idx < 128 * 16; idx += 128) {
        int row = idx >> 4, c = idx & 15;
        int kc = c >> 3, cc = c & 7;
        int g = korigin + row;
        float4 t = make_float4(0.f, 0.f, 0.f, 0.f);
        if (g >= 0 && row < 127)
            t = *(const float4*)&k[(size_t)g * DM + hcol + kc * 32 + cc * 4];
        *(float4*)(smc + 16384 + kc * 16384 + row * 128 + ((cc ^ (row & 7)) << 4)) = t;
    }
    // ---- fill Vs natural [127][68], zero below range ----
    for (int i = tid; i < 127 * 16; i += 128) {
        const int r  = i >> 4;
        const int c4 = (i & 15) << 2;
        const int g  = korigin + r;
        float4 vv = make_float4(0.f, 0.f, 0.f, 0.f);
        if (g >= 0) vv = *(const float4*)&v[(size_t)g * DM + hcol + c4];
        *(float4*)&Vs[r * ATT_PAD + c4] = vv;
    }
    __syncthreads();

    // ---- GEMM1: S = Q x K^T (M=64, N=128, K=64); warp cols 32*wid.. ----
    const int lm   = lane >> 3;
    const int lrow = lane & 7;
    const int cSel = lm >> 1;
    uint32_t aOff[4]; int aXor[4];
#pragma unroll
    for (int mi = 0; mi < 4; mi++) {
        int ar = mi * 16 + (lm & 1) * 8 + lrow;
        aOff[mi] = (uint32_t)(ar * 128); aXor[mi] = ar & 7;
    }
    uint32_t bOff[2]; int bXor[2];
#pragma unroll
    for (int pb = 0; pb < 2; pb++) {
        int br = wid * 32 + pb * 16 + (lm & 1) * 8 + lrow;
        bOff[pb] = (uint32_t)(br * 128); bXor[pb] = br & 7;
    }

    float acc1[4][4][4];
#pragma unroll
    for (int mi = 0; mi < 4; mi++)
#pragma unroll
        for (int nb = 0; nb < 4; nb++)
#pragma unroll
            for (int e2 = 0; e2 < 4; e2++) acc1[mi][nb][e2] = 0.0f;

#pragma unroll
    for (int kc = 0; kc < 2; kc++) {
        const uint32_t aBase = smem_base + (uint32_t)(kc * 8192);
        const uint32_t bBase = smem_base + 16384u + (uint32_t)(kc * 16384);
#pragma unroll
        for (int s = 0; s < 4; s++) {
            uint32_t fA[4][4];
#pragma unroll
            for (int mi = 0; mi < 4; mi++)
                LDSM4(fA[mi], aBase + aOff[mi] + (uint32_t)((((2 * s) + cSel) ^ aXor[mi]) << 4));
            uint32_t fB[4][2];
#pragma unroll
            for (int pb = 0; pb < 2; pb++) {
                uint32_t bt[4];
                LDSM4(bt, bBase + bOff[pb] + (uint32_t)((((2 * s) + cSel) ^ bXor[pb]) << 4));
                fB[2 * pb][0] = bt[0]; fB[2 * pb][1] = bt[2];
                fB[2 * pb + 1][0] = bt[1]; fB[2 * pb + 1][1] = bt[3];
            }
#pragma unroll
            for (int mi = 0; mi < 4; mi++)
#pragma unroll
                for (int nb = 0; nb < 4; nb++)
                    MMA_TF32(acc1[mi][nb], fA[mi], fB[nb][0], fB[nb][1]);
        }
    }

    // ---- band mask in fragments ----
#pragma unroll
    for (int mi = 0; mi < 4; mi++)
#pragma unroll
        for (int nb = 0; nb < 4; nb++)
#pragma unroll
            for (int e2 = 0; e2 < 4; e2++) {
                int row = mi * 16 + ((e2 >> 1) << 3) + (lane >> 2);
                int col = wid * 32 + nb * 8 + ((lane & 3) << 1) + (e2 & 1);
                bool valid = (col >= row) && (col <= row + 63) && (korigin + col >= 0);
                if (!valid) acc1[mi][nb][e2] = -INFINITY;
            }

    // ---- softmax: row max ----
    float mslot[4][2];
#pragma unroll
    for (int mi = 0; mi < 4; mi++)
#pragma unroll
        for (int hh = 0; hh < 2; hh++) {
            float m = -INFINITY;
#pragma unroll
            for (int nb = 0; nb < 4; nb++) {
                m = fmaxf(m, acc1[mi][nb][2 * hh]);
                m = fmaxf(m, acc1[mi][nb][2 * hh + 1]);
            }
            m = fmaxf(m, __shfl_xor_sync(0xffffffffu, m, 1));
            m = fmaxf(m, __shfl_xor_sync(0xffffffffu, m, 2));
            mslot[mi][hh] = m;
            if ((lane & 3) == 0)
                red1[wid * 64 + mi * 16 + 8 * hh + (lane >> 2)] = m;
        }
    __syncthreads();
    float rinv[4][2];
#pragma unroll
    for (int mi = 0; mi < 4; mi++)
#pragma unroll
        for (int hh = 0; hh < 2; hh++) {
            int row = mi * 16 + 8 * hh + (lane >> 2);
            float m = fmaxf(fmaxf(red1[row], red1[64 + row]),
                            fmaxf(red1[128 + row], red1[192 + row]));
            mslot[mi][hh] = m;
        }
    // ---- exp + row sum ----
#pragma unroll
    for (int mi = 0; mi < 4; mi++)
#pragma unroll
        for (int hh = 0; hh < 2; hh++) {
            float sum = 0.0f;
#pragma unroll
            for (int nb = 0; nb < 4; nb++) {
                float p0 = __expf(acc1[mi][nb][2 * hh]     - mslot[mi][hh]);
                float p1 = __expf(acc1[mi][nb][2 * hh + 1] - mslot[mi][hh]);
                acc1[mi][nb][2 * hh] = p0; acc1[mi][nb][2 * hh + 1] = p1;
                sum += p0 + p1;
            }
            sum += __shfl_xor_sync(0xffffffffu, sum, 1);
            sum += __shfl_xor_sync(0xffffffffu, sum, 2);
            if ((lane & 3) == 0)
                red2[wid * 64 + mi * 16 + 8 * hh + (lane >> 2)] = sum;
        }
    __syncthreads();
#pragma unroll
    for (int mi = 0; mi < 4; mi++)
#pragma unroll
        for (int hh = 0; hh < 2; hh++) {
            int row = mi * 16 + 8 * hh + (lane >> 2);
            float sum = (red2[row] + red2[64 + row]) + (red2[128 + row] + red2[192 + row]);
            rinv[mi][hh] = 1.0f / sum;
        }
    __syncthreads();   // everyone past reading red/Q/K -> safe to overlay Ps

    // ---- scatter normalized P to Ps[row][w], w = col - row ----
#pragma unroll
    for (int mi = 0; mi < 4; mi++)
#pragma unroll
        for (int nb = 0; nb < 4; nb++)
#pragma unroll
            for (int e2 = 0; e2 < 4; e2++) {
                int row = mi * 16 + ((e2 >> 1) << 3) + (lane >> 2);
                int col = wid * 32 + nb * 8 + ((lane & 3) << 1) + (e2 & 1);
                int w = col - row;
                if (w >= 0 && w < 64)
                    Ps[row * PS_STR + w] = acc1[mi][nb][e2] * rinv[mi][e2 >> 1];
            }
    __syncthreads();

    // ---- scalar AV (R7-proven): pair mapping, shared V rows ----
    const int qg = tid >> 2;
    const int hv = tid & 3;
    int ch[4];
#pragma unroll
    for (int j = 0; j < 4; j++)
        ch[j] = (hv & 1) + ((hv >> 1) << 2) + ((j & 1) << 1) + ((j >> 1) << 3);

    float accv[2][16];
#pragma unroll
    for (int d = 0; d < 16; d++) { accv[0][d] = 0.f; accv[1][d] = 0.f; }

#pragma unroll 4
    for (int i = 0; i <= 64; i++) {
        const int r = 2 * qg + i;
        const float pw0 = (i <= 63) ? Ps[(2 * qg) * PS_STR + i]         : 0.f;
        const float pw1 = (i >= 1)  ? Ps[(2 * qg + 1) * PS_STR + i - 1] : 0.f;
        const float* vr = &Vs[r * ATT_PAD];
#pragma unroll
        for (int j = 0; j < 4; j++) {
            float4 vv = *(const float4*)&vr[4 * ch[j]];
            accv[0][4*j+0] = fmaf(pw0, vv.x, accv[0][4*j+0]);
            accv[0][4*j+1] = fmaf(pw0, vv.y, accv[0][4*j+1]);
            accv[0][4*j+2] = fmaf(pw0, vv.z, accv[0][4*j+2]);
            accv[0][4*j+3] = fmaf(pw0, vv.w, accv[0][4*j+3]);
            accv[1][4*j+0] = fmaf(pw1, vv.x, accv[1][4*j+0]);
            accv[1][4*j+1] = fmaf(pw1, vv.y, accv[1][4*j+1]);
            accv[1][4*j+2] = fmaf(pw1, vv.z, accv[1][4*j+2]);
            accv[1][4*j+3] = fmaf(pw1, vv.w, accv[1][4*j+3]);
        }
    }

#pragma unroll
    for (int eq = 0; eq < 2; eq++) {
        float* orow = &o[(size_t)(qstart + 2 * qg + eq) * DM + hcol];
#pragma unroll
        for (int j = 0; j < 4; j++)
            *(float4*)&orow[4 * ch[j]] = make_float4(
                tf32_rna(accv[eq][4*j+0]), tf32_rna(accv[eq][4*j+1]),
                tf32_rna(accv[eq][4*j+2]), tf32_rna(accv[eq][4*j+3]));
    }
}

// ---------------- launch ----------------
extern "C" void kernel_launch(void* const* d_in, const int* in_sizes, int n_in,
                              void* d_out, int out_size)
{
    const float* x  = (const float*)d_in[0];
    const float* Wq = (const float*)d_in[1];
    const float* Wk = (const float*)d_in[2];
    const float* Wv = (const float*)d_in[3];
    const float* Wo = (const float*)d_in[4];
    float* out = (float*)d_out;

    float *qp, *kp, *vp, *xr, *wr, *aor;
    cudaGetSymbolAddress((void**)&qp,  g_q);
    cudaGetSymbolAddress((void**)&kp,  g_k);
    cudaGetSymbolAddress((void**)&vp,  g_v);
    cudaGetSymbolAddress((void**)&xr,  g_xr);
    cudaGetSymbolAddress((void**)&wr,  g_wr);
    cudaGetSymbolAddress((void**)&aor, g_aor);

    cudaFuncSetAttribute(gemm_tf32, cudaFuncAttributeMaxDynamicSharedMemorySize, GEMM_SMEM);
    cudaFuncSetAttribute(swattn,    cudaFuncAttributeMaxDynamicSharedMemorySize, ATT_SMEM_BYTES);

    round_all<<<dim3(S_LEN * DM / 4 / 4 / 256, 8), 256>>>(x, Wq, Wk, Wv, Wo, xr, wr);

    gemm_tf32<<<dim3(DM / 128, S_LEN / 128), 128, GEMM_SMEM>>>(xr, wr, 0, 3, qp, kp, vp);

    swattn<<<dim3(S_LEN / 64, NH), 128, ATT_SMEM_BYTES>>>(qp, kp, vp, aor);

    gemm_tf32<<<dim3(DM / 128, S_LEN / 128), 128, GEMM_SMEM>>>(aor, wr, 3, 1, out, out, out);
}

// round 14
// speedup vs baseline: 1.0588x; 1.0588x over previous
#include <cuda_runtime.h>
#include <cuda_bf16.h>
#include <cstdint>
#include <math.h>

#define S_LEN 4096
#define DM    1024
#define NH    16
#define HD    64
#define WIN   64

// ---------------- device scratch (no allocations allowed) ----------------
__device__ float g_q  [S_LEN * DM];
__device__ float g_k  [S_LEN * DM];
__device__ float g_v  [S_LEN * DM];
__device__ float g_wr [4 * DM * DM];     // tf32-rounded Wq,Wk,Wv,Wo
__device__ float g_aor[S_LEN * DM];      // attention output (raw fp32)

// ---------------- PTX helpers ----------------
__device__ __forceinline__ uint32_t smem_u32(const void* p) {
    uint32_t a;
    asm("{ .reg .u64 t; cvta.to.shared.u64 t, %1; cvt.u32.u64 %0, t; }" : "=r"(a) : "l"(p));
    return a;
}
#define CP16(dst, src) \
    asm volatile("cp.async.cg.shared.global [%0], [%1], 16;" :: "r"((uint32_t)(dst)), "l"(src) : "memory")
#define CP_COMMIT() asm volatile("cp.async.commit_group;" ::: "memory")
#define CP_WAIT1()  asm volatile("cp.async.wait_group 1;" ::: "memory")

#define LDSM4(r, addr) \
    asm volatile("ldmatrix.sync.aligned.m8n8.x4.shared.b16 {%0,%1,%2,%3}, [%4];" \
        : "=r"((r)[0]), "=r"((r)[1]), "=r"((r)[2]), "=r"((r)[3]) : "r"(addr))

#define MMA_TF32(d, a, b0v, b1v) \
    asm volatile("mma.sync.aligned.m16n8k8.row.col.f32.tf32.tf32.f32 " \
        "{%0,%1,%2,%3}, {%4,%5,%6,%7}, {%8,%9}, {%0,%1,%2,%3};" \
        : "+f"((d)[0]), "+f"((d)[1]), "+f"((d)[2]), "+f"((d)[3]) \
        : "r"((a)[0]), "r"((a)[1]), "r"((a)[2]), "r"((a)[3]), "r"(b0v), "r"(b1v))

// in-register tf32 rounding (round-to-nearest-even on the 10-bit mantissa)
#define TF32R(r) asm("cvt.rna.tf32.f32 %0, %0;" : "+r"(r))

__device__ __forceinline__ float tf32_rna(float x) {
    uint32_t t;
    asm("cvt.rna.tf32.f32 %0, %1;" : "=r"(t) : "f"(x));
    return __uint_as_float(t);
}

// ---------------- weight pre-round kernel (weights only) ----------------
__global__ void round_w4(const float* __restrict__ Wq, const float* __restrict__ Wk,
                         const float* __restrict__ Wv, const float* __restrict__ Wo,
                         float* __restrict__ wr) {
    const int y = blockIdx.y;
    const float* W = y == 0 ? Wq : (y == 1 ? Wk : (y == 2 ? Wv : Wo));
    int i = blockIdx.x * blockDim.x + threadIdx.x;
    float4 f = ((const float4*)W)[i];
    ((float4*)(wr + (size_t)y * DM * DM))[i] =
        make_float4(tf32_rna(f.x), tf32_rna(f.y), tf32_rna(f.z), tf32_rna(f.w));
}

// ---------------------------------------------------------------------------
// tf32 GEMM v8: R11-frozen structure (CTA 128x128, BK=32, 3-stage, 2 CTAs/SM,
// in-kernel z-loop).  NEW: A-fragments rounded to tf32 in-register (rna) after
// LDSM — A may be raw fp32 (x, aor); B (weights) remains pre-rounded.
// ---------------------------------------------------------------------------
#define TILE_B  16384
#define STAGE_B (2 * TILE_B)
#define NSTAGE  3
#define GEMM_SMEM (NSTAGE * STAGE_B)

__global__ __launch_bounds__(128, 2) void gemm_tf32(
    const float* __restrict__ A, const float* __restrict__ Wr,
    int w_off, int nz,
    float* __restrict__ C0, float* __restrict__ C1, float* __restrict__ C2)
{
    extern __shared__ char sm[];
    const uint32_t smem_base = smem_u32(sm);
    const int tid  = threadIdx.x;
    const int lane = tid & 31;
    const int wid  = tid >> 5;
    const int wm   = wid & 1;
    const int wn   = wid >> 1;
    const int m0 = blockIdx.y * 128;
    const int n0 = blockIdx.x * 128;

    uint32_t swo[8], gA[8], gB[8];
#pragma unroll
    for (int jj = 0; jj < 8; jj++) {
        int qq = tid + 128 * jj;
        int r = qq >> 3, c = qq & 7;
        swo[jj] = (uint32_t)(r * 128 + ((c ^ (r & 7)) << 4));
        gA[jj] = (uint32_t)((m0 + r) * DM + c * 4);
        gB[jj] = (uint32_t)((n0 + r) * DM + c * 4);
    }

    const int lm   = lane >> 3;
    const int lrow = lane & 7;
    const int cSel = lm >> 1;
    uint32_t aOff[4]; int aXor[4];
#pragma unroll
    for (int mi = 0; mi < 4; mi++) {
        int ar = wm * 64 + mi * 16 + (lm & 1) * 8 + lrow;
        aOff[mi] = (uint32_t)(ar * 128); aXor[mi] = ar & 7;
    }
    uint32_t bOff[4]; int bXor[4];
#pragma unroll
    for (int pb = 0; pb < 4; pb++) {
        int br = wn * 64 + pb * 16 + (lm & 1) * 8 + lrow;
        bOff[pb] = (uint32_t)(br * 128); bXor[pb] = br & 7;
    }

    const int ITERS = DM / 32;   // 32

    for (int zi = 0; zi < nz; zi++) {
        const float* B = Wr + (size_t)(w_off + zi) * DM * DM;
        float* C = zi == 0 ? C0 : (zi == 1 ? C1 : C2);

        float acc[4][8][4];
#pragma unroll
        for (int mi = 0; mi < 4; mi++)
#pragma unroll
            for (int nb = 0; nb < 8; nb++)
#pragma unroll
                for (int e2 = 0; e2 < 4; e2++) acc[mi][nb][e2] = 0.0f;

        auto issue = [&](int t) {
            const uint32_t sb = smem_base + (uint32_t)(t % NSTAGE) * STAGE_B;
            const uint32_t kt = (uint32_t)(t * 32);
#pragma unroll
            for (int jj = 0; jj < 8; jj++) {
                CP16(sb + swo[jj],          (const char*)A + (size_t)(gA[jj] + kt) * 4);
                CP16(sb + TILE_B + swo[jj], (const char*)B + (size_t)(gB[jj] + kt) * 4);
            }
            CP_COMMIT();
        };

        __syncthreads();
        issue(0); issue(1);

        for (int t = 0; t < ITERS; t++) {
            CP_WAIT1();
            __syncthreads();
            if (t + 2 < ITERS) issue(t + 2);

            const uint32_t sb = smem_base + (uint32_t)(t % NSTAGE) * STAGE_B;
            const uint32_t aBase = sb, bBase = sb + TILE_B;

#pragma unroll
            for (int s = 0; s < 4; s++) {
                uint32_t fA[4][4];
#pragma unroll
                for (int mi = 0; mi < 4; mi++) {
                    LDSM4(fA[mi], aBase + aOff[mi] + (uint32_t)((((2 * s) + cSel) ^ aXor[mi]) << 4));
                    TF32R(fA[mi][0]); TF32R(fA[mi][1]); TF32R(fA[mi][2]); TF32R(fA[mi][3]);
                }
                uint32_t fB[8][2];
#pragma unroll
                for (int pb = 0; pb < 4; pb++) {
                    uint32_t bt[4];
                    LDSM4(bt, bBase + bOff[pb] + (uint32_t)((((2 * s) + cSel) ^ bXor[pb]) << 4));
                    fB[2 * pb][0] = bt[0]; fB[2 * pb][1] = bt[2];
                    fB[2 * pb + 1][0] = bt[1]; fB[2 * pb + 1][1] = bt[3];
                }
#pragma unroll
                for (int mi = 0; mi < 4; mi++)
#pragma unroll
                    for (int nb = 0; nb < 8; nb++)
                        MMA_TF32(acc[mi][nb], fA[mi], fB[nb][0], fB[nb][1]);
            }
        }

        const int crow0 = m0 + wm * 64 + (lane >> 2);
        const int ccol0 = n0 + wn * 64 + (lane & 3) * 2;
#pragma unroll
        for (int mi = 0; mi < 4; mi++) {
#pragma unroll
            for (int nb = 0; nb < 8; nb++) {
                const int row = crow0 + mi * 16;
                const int col = ccol0 + nb * 8;
                *(float2*)&C[(size_t)row * DM + col]       = make_float2(acc[mi][nb][0], acc[mi][nb][1]);
                *(float2*)&C[(size_t)(row + 8) * DM + col] = make_float2(acc[mi][nb][2], acc[mi][nb][3]);
            }
        }
    }
}

// ---------------------------------------------------------------------------
// Sliding-window attention v4 (FROZEN — R7/R11 proven, 76.7us).
// Output written as raw fp32 (Wo GEMM rounds A-fragments in-register).
// ---------------------------------------------------------------------------
#define ATT_PAD 68
#define ATT_ROWS 127
#define PS_STR 67
#define ATT_SMEM_BYTES (2 * ATT_ROWS * ATT_PAD * 4)   // 69088

__global__ __launch_bounds__(128, 3) void swattn(
    const float* __restrict__ q, const float* __restrict__ k,
    const float* __restrict__ v, float* __restrict__ o)
{
    extern __shared__ float smf[];
    float* Ks = smf;
    float* Vs = smf + ATT_ROWS * ATT_PAD;
    float* Ps = smf;

    const int qstart  = blockIdx.x * 64;
    const int h       = blockIdx.y;
    const int korigin = qstart - (WIN - 1);
    const int hcol    = h * HD;

    const int tid = threadIdx.x;
    const int qg  = tid >> 2;
    const int hv  = tid & 3;
    const int e   = hv & 1;

    int ch[4];
#pragma unroll
    for (int j = 0; j < 4; j++)
        ch[j] = (hv & 1) + ((hv >> 1) << 2) + ((j & 1) << 1) + ((j >> 1) << 3);

    for (int i = tid; i < ATT_ROWS * 16; i += 128) {
        const int r  = i >> 4;
        const int c4 = (i & 15) << 2;
        const int g  = korigin + r;
        float4 kk = make_float4(0.f, 0.f, 0.f, 0.f);
        float4 vv = kk;
        if (g >= 0) {
            kk = *(const float4*)&k[(size_t)g * DM + hcol + c4];
            vv = *(const float4*)&v[(size_t)g * DM + hcol + c4];
        }
        *(float4*)&Ks[r * ATT_PAD + c4] = kk;
        *(float4*)&Vs[r * ATT_PAD + c4] = vv;
    }

    float qreg[2][16];
#pragma unroll
    for (int eq = 0; eq < 2; eq++) {
        const float* qrow = &q[(size_t)(qstart + 2 * qg + eq) * DM + hcol];
#pragma unroll
        for (int j = 0; j < 4; j++) {
            float4 t4 = *(const float4*)&qrow[4 * ch[j]];
            qreg[eq][4*j+0] = t4.x * 0.125f;
            qreg[eq][4*j+1] = t4.y * 0.125f;
            qreg[eq][4*j+2] = t4.z * 0.125f;
            qreg[eq][4*j+3] = t4.w * 0.125f;
        }
    }
    __syncthreads();

    float s[65];
#pragma unroll
    for (int i = 0; i <= 64; i++) {
        const int r = 2 * qg + i;
        const float* kr = &Ks[r * ATT_PAD];
        float u0 = 0.f, u1 = 0.f, w0 = 0.f, w1 = 0.f;
#pragma unroll
        for (int j = 0; j < 4; j++) {
            float4 kk = *(const float4*)&kr[4 * ch[j]];
            if (j & 1) {
                u1 = fmaf(qreg[0][4*j+0], kk.x, u1); u1 = fmaf(qreg[0][4*j+1], kk.y, u1);
                u1 = fmaf(qreg[0][4*j+2], kk.z, u1); u1 = fmaf(qreg[0][4*j+3], kk.w, u1);
                w1 = fmaf(qreg[1][4*j+0], kk.x, w1); w1 = fmaf(qreg[1][4*j+1], kk.y, w1);
                w1 = fmaf(qreg[1][4*j+2], kk.z, w1); w1 = fmaf(qreg[1][4*j+3], kk.w, w1);
            } else {
                u0 = fmaf(qreg[0][4*j+0], kk.x, u0); u0 = fmaf(qreg[0][4*j+1], kk.y, u0);
                u0 = fmaf(qreg[0][4*j+2], kk.z, u0); u0 = fmaf(qreg[0][4*j+3], kk.w, u0);
                w0 = fmaf(qreg[1][4*j+0], kk.x, w0); w0 = fmaf(qreg[1][4*j+1], kk.y, w0);
                w0 = fmaf(qreg[1][4*j+2], kk.z, w0); w0 = fmaf(qreg[1][4*j+3], kk.w, w0);
            }
        }
        float u = u0 + u1;
        float wv = w0 + w1;
        u  += __shfl_xor_sync(0xffffffffu, u, 1);
        u  += __shfl_xor_sync(0xffffffffu, u, 2);
        wv += __shfl_xor_sync(0xffffffffu, wv, 1);
        wv += __shfl_xor_sync(0xffffffffu, wv, 2);
        const float sc = e ? wv : u;
        const bool valid = (korigin + r >= 0) && (e ? (i >= 1) : (i <= 63));
        s[i] = valid ? sc : -INFINITY;
    }

    float mx = -INFINITY;
#pragma unroll
    for (int i = 0; i <= 64; i++) mx = fmaxf(mx, s[i]);
    float sum = 0.0f;
#pragma unroll
    for (int i = 0; i <= 64; i++) { s[i] = __expf(s[i] - mx); sum += s[i]; }
    const float inv = 1.0f / sum;
#pragma unroll
    for (int i = 0; i <= 64; i++) s[i] *= inv;

    __syncthreads();

    if (hv < 2) {
        const int base = (2 * qg + e) * PS_STR;
#pragma unroll
        for (int i = 0; i <= 64; i++) {
            const int w = i - e;
            if (w >= 0 && w <= 63) Ps[base + w] = s[i];
        }
    }
    __syncthreads();

    float accv[2][16];
#pragma unroll
    for (int d = 0; d < 16; d++) { accv[0][d] = 0.f; accv[1][d] = 0.f; }

#pragma unroll 4
    for (int i = 0; i <= 64; i++) {
        const int r = 2 * qg + i;
        const float pw0 = (i <= 63) ? Ps[(2 * qg) * PS_STR + i]         : 0.f;
        const float pw1 = (i >= 1)  ? Ps[(2 * qg + 1) * PS_STR + i - 1] : 0.f;
        const float* vr = &Vs[r * ATT_PAD];
#pragma unroll
        for (int j = 0; j < 4; j++) {
            float4 vv = *(const float4*)&vr[4 * ch[j]];
            accv[0][4*j+0] = fmaf(pw0, vv.x, accv[0][4*j+0]);
            accv[0][4*j+1] = fmaf(pw0, vv.y, accv[0][4*j+1]);
            accv[0][4*j+2] = fmaf(pw0, vv.z, accv[0][4*j+2]);
            accv[0][4*j+3] = fmaf(pw0, vv.w, accv[0][4*j+3]);
            accv[1][4*j+0] = fmaf(pw1, vv.x, accv[1][4*j+0]);
            accv[1][4*j+1] = fmaf(pw1, vv.y, accv[1][4*j+1]);
            accv[1][4*j+2] = fmaf(pw1, vv.z, accv[1][4*j+2]);
            accv[1][4*j+3] = fmaf(pw1, vv.w, accv[1][4*j+3]);
        }
    }

#pragma unroll
    for (int eq = 0; eq < 2; eq++) {
        float* orow = &o[(size_t)(qstart + 2 * qg + eq) * DM + hcol];
#pragma unroll
        for (int j = 0; j < 4; j++)
            *(float4*)&orow[4 * ch[j]] = make_float4(
                accv[eq][4*j+0], accv[eq][4*j+1],
                accv[eq][4*j+2], accv[eq][4*j+3]);
    }
}

// ---------------- launch ----------------
extern "C" void kernel_launch(void* const* d_in, const int* in_sizes, int n_in,
                              void* d_out, int out_size)
{
    const float* x  = (const float*)d_in[0];
    const float* Wq = (const float*)d_in[1];
    const float* Wk = (const float*)d_in[2];
    const float* Wv = (const float*)d_in[3];
    const float* Wo = (const float*)d_in[4];
    float* out = (float*)d_out;

    float *qp, *kp, *vp, *wr, *aor;
    cudaGetSymbolAddress((void**)&qp,  g_q);
    cudaGetSymbolAddress((void**)&kp,  g_k);
    cudaGetSymbolAddress((void**)&vp,  g_v);
    cudaGetSymbolAddress((void**)&wr,  g_wr);
    cudaGetSymbolAddress((void**)&aor, g_aor);

    cudaFuncSetAttribute(gemm_tf32, cudaFuncAttributeMaxDynamicSharedMemorySize, GEMM_SMEM);
    cudaFuncSetAttribute(swattn,    cudaFuncAttributeMaxDynamicSharedMemorySize, ATT_SMEM_BYTES);

    // 1. pre-round ONLY the weights to tf32 (x / aor rounded in-register in GEMM)
    round_w4<<<dim3(DM * DM / 4 / 256, 4), 256>>>(Wq, Wk, Wv, Wo, wr);

    // 2. QKV projections: 256 CTAs, 3 weight matrices per CTA (no wave tail)
    gemm_tf32<<<dim3(DM / 128, S_LEN / 128), 128, GEMM_SMEM>>>(x, wr, 0, 3, qp, kp, vp);

    // 3. sliding-window attention
    swattn<<<dim3(S_LEN / 64, NH), 128, ATT_SMEM_BYTES>>>(qp, kp, vp, aor);

    // 4. output projection
    gemm_tf32<<<dim3(DM / 128, S_LEN / 128), 128, GEMM_SMEM>>>(aor, wr, 3, 1, out, out, out);
}

// round 15
// speedup vs baseline: 1.0659x; 1.0067x over previous
#include <cuda_runtime.h>
#include <cuda_bf16.h>
#include <cstdint>
#include <math.h>

#define S_LEN 4096
#define DM    1024
#define NH    16
#define HD    64
#define WIN   64

// ---------------- device scratch (no allocations allowed) ----------------
__device__ float g_q  [S_LEN * DM];
__device__ float g_k  [S_LEN * DM];
__device__ float g_v  [S_LEN * DM];
__device__ float g_xr [S_LEN * DM];      // tf32-rounded x
__device__ float g_wr [4 * DM * DM];     // tf32-rounded Wq,Wk,Wv,Wo
__device__ float g_aor[S_LEN * DM];      // tf32-rounded attention output

// ---------------- PTX helpers ----------------
__device__ __forceinline__ uint32_t smem_u32(const void* p) {
    uint32_t a;
    asm("{ .reg .u64 t; cvta.to.shared.u64 t, %1; cvt.u32.u64 %0, t; }" : "=r"(a) : "l"(p));
    return a;
}
#define CP16(dst, src) \
    asm volatile("cp.async.cg.shared.global [%0], [%1], 16;" :: "r"((uint32_t)(dst)), "l"(src) : "memory")
#define CP_COMMIT() asm volatile("cp.async.commit_group;" ::: "memory")
#define CP_WAIT1()  asm volatile("cp.async.wait_group 1;" ::: "memory")

#define LDSM4(r, addr) \
    asm volatile("ldmatrix.sync.aligned.m8n8.x4.shared.b16 {%0,%1,%2,%3}, [%4];" \
        : "=r"((r)[0]), "=r"((r)[1]), "=r"((r)[2]), "=r"((r)[3]) : "r"(addr))

#define MMA_TF32(d, a, b0v, b1v) \
    asm volatile("mma.sync.aligned.m16n8k8.row.col.f32.tf32.tf32.f32 " \
        "{%0,%1,%2,%3}, {%4,%5,%6,%7}, {%8,%9}, {%0,%1,%2,%3};" \
        : "+f"((d)[0]), "+f"((d)[1]), "+f"((d)[2]), "+f"((d)[3]) \
        : "r"((a)[0]), "r"((a)[1]), "r"((a)[2]), "r"((a)[3]), "r"(b0v), "r"(b1v))

__device__ __forceinline__ float tf32_rna(float x) {
    uint32_t t;
    asm("cvt.rna.tf32.f32 %0, %1;" : "=r"(t) : "f"(x));
    return __uint_as_float(t);
}

// ---------------- tf32 pre-round kernel v2: 4 float4 per thread ----------
// y slices: 0..3 -> quarters of x, 4..7 -> Wq..Wo.  Each slice = 256K float4;
// 256 blocks x 256 threads x 4 float4 (batched loads -> MLP=4).
__global__ void round_all(const float* __restrict__ x,
                          const float* __restrict__ Wq, const float* __restrict__ Wk,
                          const float* __restrict__ Wv, const float* __restrict__ Wo,
                          float* __restrict__ xr, float* __restrict__ wr) {
    const int y = blockIdx.y;
    const float* src;
    float* dst;
    if (y < 4) {
        src = x  + (size_t)y * (S_LEN * DM / 4);
        dst = xr + (size_t)y * (S_LEN * DM / 4);
    } else {
        const float* W = y == 4 ? Wq : (y == 5 ? Wk : (y == 6 ? Wv : Wo));
        src = W;
        dst = wr + (size_t)(y - 4) * DM * DM;
    }
    const int base = (blockIdx.x * 256 + threadIdx.x) * 4;   // float4 index
    float4 f0 = ((const float4*)src)[base + 0];
    float4 f1 = ((const float4*)src)[base + 1];
    float4 f2 = ((const float4*)src)[base + 2];
    float4 f3 = ((const float4*)src)[base + 3];
    ((float4*)dst)[base + 0] = make_float4(tf32_rna(f0.x), tf32_rna(f0.y), tf32_rna(f0.z), tf32_rna(f0.w));
    ((float4*)dst)[base + 1] = make_float4(tf32_rna(f1.x), tf32_rna(f1.y), tf32_rna(f1.z), tf32_rna(f1.w));
    ((float4*)dst)[base + 2] = make_float4(tf32_rna(f2.x), tf32_rna(f2.y), tf32_rna(f2.z), tf32_rna(f2.w));
    ((float4*)dst)[base + 3] = make_float4(tf32_rna(f3.x), tf32_rna(f3.y), tf32_rna(f3.z), tf32_rna(f3.w));
}

// ---------------------------------------------------------------------------
// tf32 GEMM v7 (FROZEN — R11 exact): CTA 128x128, BK=32, 3-stage, 2 CTAs/SM,
// in-kernel z-loop (grid=256, no wave tail).  No in-register rounding.
// ---------------------------------------------------------------------------
#define TILE_B  16384
#define STAGE_B (2 * TILE_B)
#define NSTAGE  3
#define GEMM_SMEM (NSTAGE * STAGE_B)

__global__ __launch_bounds__(128, 2) void gemm_tf32(
    const float* __restrict__ A, const float* __restrict__ Wr,
    int w_off, int nz,
    float* __restrict__ C0, float* __restrict__ C1, float* __restrict__ C2)
{
    extern __shared__ char sm[];
    const uint32_t smem_base = smem_u32(sm);
    const int tid  = threadIdx.x;
    const int lane = tid & 31;
    const int wid  = tid >> 5;
    const int wm   = wid & 1;
    const int wn   = wid >> 1;
    const int m0 = blockIdx.y * 128;
    const int n0 = blockIdx.x * 128;

    uint32_t swo[8], gA[8], gB[8];
#pragma unroll
    for (int jj = 0; jj < 8; jj++) {
        int qq = tid + 128 * jj;
        int r = qq >> 3, c = qq & 7;
        swo[jj] = (uint32_t)(r * 128 + ((c ^ (r & 7)) << 4));
        gA[jj] = (uint32_t)((m0 + r) * DM + c * 4);
        gB[jj] = (uint32_t)((n0 + r) * DM + c * 4);
    }

    const int lm   = lane >> 3;
    const int lrow = lane & 7;
    const int cSel = lm >> 1;
    uint32_t aOff[4]; int aXor[4];
#pragma unroll
    for (int mi = 0; mi < 4; mi++) {
        int ar = wm * 64 + mi * 16 + (lm & 1) * 8 + lrow;
        aOff[mi] = (uint32_t)(ar * 128); aXor[mi] = ar & 7;
    }
    uint32_t bOff[4]; int bXor[4];
#pragma unroll
    for (int pb = 0; pb < 4; pb++) {
        int br = wn * 64 + pb * 16 + (lm & 1) * 8 + lrow;
        bOff[pb] = (uint32_t)(br * 128); bXor[pb] = br & 7;
    }

    const int ITERS = DM / 32;   // 32

    for (int zi = 0; zi < nz; zi++) {
        const float* B = Wr + (size_t)(w_off + zi) * DM * DM;
        float* C = zi == 0 ? C0 : (zi == 1 ? C1 : C2);

        float acc[4][8][4];
#pragma unroll
        for (int mi = 0; mi < 4; mi++)
#pragma unroll
            for (int nb = 0; nb < 8; nb++)
#pragma unroll
                for (int e2 = 0; e2 < 4; e2++) acc[mi][nb][e2] = 0.0f;

        auto issue = [&](int t) {
            const uint32_t sb = smem_base + (uint32_t)(t % NSTAGE) * STAGE_B;
            const uint32_t kt = (uint32_t)(t * 32);
#pragma unroll
            for (int jj = 0; jj < 8; jj++) {
                CP16(sb + swo[jj],          (const char*)A + (size_t)(gA[jj] + kt) * 4);
                CP16(sb + TILE_B + swo[jj], (const char*)B + (size_t)(gB[jj] + kt) * 4);
            }
            CP_COMMIT();
        };

        __syncthreads();
        issue(0); issue(1);

        for (int t = 0; t < ITERS; t++) {
            CP_WAIT1();
            __syncthreads();
            if (t + 2 < ITERS) issue(t + 2);

            const uint32_t sb = smem_base + (uint32_t)(t % NSTAGE) * STAGE_B;
            const uint32_t aBase = sb, bBase = sb + TILE_B;

#pragma unroll
            for (int s = 0; s < 4; s++) {
                uint32_t fA[4][4];
#pragma unroll
                for (int mi = 0; mi < 4; mi++)
                    LDSM4(fA[mi], aBase + aOff[mi] + (uint32_t)((((2 * s) + cSel) ^ aXor[mi]) << 4));
                uint32_t fB[8][2];
#pragma unroll
                for (int pb = 0; pb < 4; pb++) {
                    uint32_t bt[4];
                    LDSM4(bt, bBase + bOff[pb] + (uint32_t)((((2 * s) + cSel) ^ bXor[pb]) << 4));
                    fB[2 * pb][0] = bt[0]; fB[2 * pb][1] = bt[2];
                    fB[2 * pb + 1][0] = bt[1]; fB[2 * pb + 1][1] = bt[3];
                }
#pragma unroll
                for (int mi = 0; mi < 4; mi++)
#pragma unroll
                    for (int nb = 0; nb < 8; nb++)
                        MMA_TF32(acc[mi][nb], fA[mi], fB[nb][0], fB[nb][1]);
            }
        }

        const int crow0 = m0 + wm * 64 + (lane >> 2);
        const int ccol0 = n0 + wn * 64 + (lane & 3) * 2;
#pragma unroll
        for (int mi = 0; mi < 4; mi++) {
#pragma unroll
            for (int nb = 0; nb < 8; nb++) {
                const int row = crow0 + mi * 16;
                const int col = ccol0 + nb * 8;
                *(float2*)&C[(size_t)row * DM + col]       = make_float2(acc[mi][nb][0], acc[mi][nb][1]);
                *(float2*)&C[(size_t)(row + 8) * DM + col] = make_float2(acc[mi][nb][2], acc[mi][nb][3]);
            }
        }
    }
}

// ---------------------------------------------------------------------------
// Sliding-window attention v4 (FROZEN — R11 exact, emits tf32-rounded output).
// ---------------------------------------------------------------------------
#define ATT_PAD 68
#define ATT_ROWS 127
#define PS_STR 67
#define ATT_SMEM_BYTES (2 * ATT_ROWS * ATT_PAD * 4)   // 69088

__global__ __launch_bounds__(128, 3) void swattn(
    const float* __restrict__ q, const float* __restrict__ k,
    const float* __restrict__ v, float* __restrict__ o)
{
    extern __shared__ float smf[];
    float* Ks = smf;
    float* Vs = smf + ATT_ROWS * ATT_PAD;
    float* Ps = smf;

    const int qstart  = blockIdx.x * 64;
    const int h       = blockIdx.y;
    const int korigin = qstart - (WIN - 1);
    const int hcol    = h * HD;

    const int tid = threadIdx.x;
    const int qg  = tid >> 2;
    const int hv  = tid & 3;
    const int e   = hv & 1;

    int ch[4];
#pragma unroll
    for (int j = 0; j < 4; j++)
        ch[j] = (hv & 1) + ((hv >> 1) << 2) + ((j & 1) << 1) + ((j >> 1) << 3);

    for (int i = tid; i < ATT_ROWS * 16; i += 128) {
        const int r  = i >> 4;
        const int c4 = (i & 15) << 2;
        const int g  = korigin + r;
        float4 kk = make_float4(0.f, 0.f, 0.f, 0.f);
        float4 vv = kk;
        if (g >= 0) {
            kk = *(const float4*)&k[(size_t)g * DM + hcol + c4];
            vv = *(const float4*)&v[(size_t)g * DM + hcol + c4];
        }
        *(float4*)&Ks[r * ATT_PAD + c4] = kk;
        *(float4*)&Vs[r * ATT_PAD + c4] = vv;
    }

    float qreg[2][16];
#pragma unroll
    for (int eq = 0; eq < 2; eq++) {
        const float* qrow = &q[(size_t)(qstart + 2 * qg + eq) * DM + hcol];
#pragma unroll
        for (int j = 0; j < 4; j++) {
            float4 t4 = *(const float4*)&qrow[4 * ch[j]];
            qreg[eq][4*j+0] = t4.x * 0.125f;
            qreg[eq][4*j+1] = t4.y * 0.125f;
            qreg[eq][4*j+2] = t4.z * 0.125f;
            qreg[eq][4*j+3] = t4.w * 0.125f;
        }
    }
    __syncthreads();

    float s[65];
#pragma unroll
    for (int i = 0; i <= 64; i++) {
        const int r = 2 * qg + i;
        const float* kr = &Ks[r * ATT_PAD];
        float u0 = 0.f, u1 = 0.f, w0 = 0.f, w1 = 0.f;
#pragma unroll
        for (int j = 0; j < 4; j++) {
            float4 kk = *(const float4*)&kr[4 * ch[j]];
            if (j & 1) {
                u1 = fmaf(qreg[0][4*j+0], kk.x, u1); u1 = fmaf(qreg[0][4*j+1], kk.y, u1);
                u1 = fmaf(qreg[0][4*j+2], kk.z, u1); u1 = fmaf(qreg[0][4*j+3], kk.w, u1);
                w1 = fmaf(qreg[1][4*j+0], kk.x, w1); w1 = fmaf(qreg[1][4*j+1], kk.y, w1);
                w1 = fmaf(qreg[1][4*j+2], kk.z, w1); w1 = fmaf(qreg[1][4*j+3], kk.w, w1);
            } else {
                u0 = fmaf(qreg[0][4*j+0], kk.x, u0); u0 = fmaf(qreg[0][4*j+1], kk.y, u0);
                u0 = fmaf(qreg[0][4*j+2], kk.z, u0); u0 = fmaf(qreg[0][4*j+3], kk.w, u0);
                w0 = fmaf(qreg[1][4*j+0], kk.x, w0); w0 = fmaf(qreg[1][4*j+1], kk.y, w0);
                w0 = fmaf(qreg[1][4*j+2], kk.z, w0); w0 = fmaf(qreg[1][4*j+3], kk.w, w0);
            }
        }
        float u = u0 + u1;
        float wv = w0 + w1;
        u  += __shfl_xor_sync(0xffffffffu, u, 1);
        u  += __shfl_xor_sync(0xffffffffu, u, 2);
        wv += __shfl_xor_sync(0xffffffffu, wv, 1);
        wv += __shfl_xor_sync(0xffffffffu, wv, 2);
        const float sc = e ? wv : u;
        const bool valid = (korigin + r >= 0) && (e ? (i >= 1) : (i <= 63));
        s[i] = valid ? sc : -INFINITY;
    }

    float mx = -INFINITY;
#pragma unroll
    for (int i = 0; i <= 64; i++) mx = fmaxf(mx, s[i]);
    float sum = 0.0f;
#pragma unroll
    for (int i = 0; i <= 64; i++) { s[i] = __expf(s[i] - mx); sum += s[i]; }
    const float inv = 1.0f / sum;
#pragma unroll
    for (int i = 0; i <= 64; i++) s[i] *= inv;

    __syncthreads();

    if (hv < 2) {
        const int base = (2 * qg + e) * PS_STR;
#pragma unroll
        for (int i = 0; i <= 64; i++) {
            const int w = i - e;
            if (w >= 0 && w <= 63) Ps[base + w] = s[i];
        }
    }
    __syncthreads();

    float accv[2][16];
#pragma unroll
    for (int d = 0; d < 16; d++) { accv[0][d] = 0.f; accv[1][d] = 0.f; }

#pragma unroll 4
    for (int i = 0; i <= 64; i++) {
        const int r = 2 * qg + i;
        const float pw0 = (i <= 63) ? Ps[(2 * qg) * PS_STR + i]         : 0.f;
        const float pw1 = (i >= 1)  ? Ps[(2 * qg + 1) * PS_STR + i - 1] : 0.f;
        const float* vr = &Vs[r * ATT_PAD];
#pragma unroll
        for (int j = 0; j < 4; j++) {
            float4 vv = *(const float4*)&vr[4 * ch[j]];
            accv[0][4*j+0] = fmaf(pw0, vv.x, accv[0][4*j+0]);
            accv[0][4*j+1] = fmaf(pw0, vv.y, accv[0][4*j+1]);
            accv[0][4*j+2] = fmaf(pw0, vv.z, accv[0][4*j+2]);
            accv[0][4*j+3] = fmaf(pw0, vv.w, accv[0][4*j+3]);
            accv[1][4*j+0] = fmaf(pw1, vv.x, accv[1][4*j+0]);
            accv[1][4*j+1] = fmaf(pw1, vv.y, accv[1][4*j+1]);
            accv[1][4*j+2] = fmaf(pw1, vv.z, accv[1][4*j+2]);
            accv[1][4*j+3] = fmaf(pw1, vv.w, accv[1][4*j+3]);
        }
    }

#pragma unroll
    for (int eq = 0; eq < 2; eq++) {
        float* orow = &o[(size_t)(qstart + 2 * qg + eq) * DM + hcol];
#pragma unroll
        for (int j = 0; j < 4; j++)
            *(float4*)&orow[4 * ch[j]] = make_float4(
                tf32_rna(accv[eq][4*j+0]), tf32_rna(accv[eq][4*j+1]),
                tf32_rna(accv[eq][4*j+2]), tf32_rna(accv[eq][4*j+3]));
    }
}

// ---------------- launch ----------------
extern "C" void kernel_launch(void* const* d_in, const int* in_sizes, int n_in,
                              void* d_out, int out_size)
{
    const float* x  = (const float*)d_in[0];
    const float* Wq = (const float*)d_in[1];
    const float* Wk = (const float*)d_in[2];
    const float* Wv = (const float*)d_in[3];
    const float* Wo = (const float*)d_in[4];
    float* out = (float*)d_out;

    float *qp, *kp, *vp, *xr, *wr, *aor;
    cudaGetSymbolAddress((void**)&qp,  g_q);
    cudaGetSymbolAddress((void**)&kp,  g_k);
    cudaGetSymbolAddress((void**)&vp,  g_v);
    cudaGetSymbolAddress((void**)&xr,  g_xr);
    cudaGetSymbolAddress((void**)&wr,  g_wr);
    cudaGetSymbolAddress((void**)&aor, g_aor);

    cudaFuncSetAttribute(gemm_tf32, cudaFuncAttributeMaxDynamicSharedMemorySize, GEMM_SMEM);
    cudaFuncSetAttribute(swattn,    cudaFuncAttributeMaxDynamicSharedMemorySize, ATT_SMEM_BYTES);

    // 1. pre-round x and all W to tf32 (4 float4/thread, MLP=4)
    round_all<<<dim3(256, 8), 256>>>(x, Wq, Wk, Wv, Wo, xr, wr);

    // 2. QKV projections: 256 CTAs, 3 weight matrices per CTA (no wave tail)
    gemm_tf32<<<dim3(DM / 128, S_LEN / 128), 128, GEMM_SMEM>>>(xr, wr, 0, 3, qp, kp, vp);

    // 3. sliding-window attention (emits tf32-rounded output)
    swattn<<<dim3(S_LEN / 64, NH), 128, ATT_SMEM_BYTES>>>(qp, kp, vp, aor);

    // 4. output projection
    gemm_tf32<<<dim3(DM / 128, S_LEN / 128), 128, GEMM_SMEM>>>(aor, wr, 3, 1, out, out, out);
}